// round 6
// baseline (speedup 1.0000x reference)
#include <cuda_runtime.h>
#include <math.h>

#define CC 10

static const int BLOCK = 256;
static const int GRID  = 1184;
static const int WARPS_PER_BLOCK = 8;
static const int NWARPS = GRID * WARPS_PER_BLOCK;

// Per-block partials: [block][stat], 0..9 = sum p, 10..19 = sum p^2,
// 20..29 = sum logits v, 30 = sum of per-row log-sum-exp M.
// (sum log p[i] = sum_v[i] - sum_M)
__device__ double g_partials[GRID][32];

// ---------------------------------------------------------------------------
// Kernel 1: stats with warp-level shared staging.
// Each warp-tile = 64 rows = 160 float4 = 2560B: coalesced LDG.128 -> STS.128
// linear -> each lane LDS.128 x5 for its 2 contiguous rows (80B aligned).
// ---------------------------------------------------------------------------
__global__ __launch_bounds__(256, 3) void ed_stats(const float* __restrict__ x, int n) {
    __shared__ float4 stage[WARPS_PER_BLOCK][160];

    const int lane = threadIdx.x & 31;
    const int w    = threadIdx.x >> 5;
    const int gw   = blockIdx.x * WARPS_PER_BLOCK + w;

    float ap [CC];   // sum p
    float ap2[CC];   // sum p^2
    float sv [CC];   // sum v (logits)
    float sM = 0.f;  // sum log-sum-exp
#pragma unroll
    for (int i = 0; i < CC; i++) { ap[i] = 0.f; ap2[i] = 0.f; sv[i] = 0.f; }

    const float4* __restrict__ x4 = reinterpret_cast<const float4*>(x);
    const int nTiles = n >> 6;   // 64 rows per tile

    for (int t = gw; t < nTiles; t += NWARPS) {
        const float4* src = x4 + (size_t)t * 160;
        float4 v0 = src[lane      ];
        float4 v1 = src[lane +  32];
        float4 v2 = src[lane +  64];
        float4 v3 = src[lane +  96];
        float4 v4 = src[lane + 128];
        __syncwarp();                    // prior tile fully consumed
        stage[w][lane      ] = v0;
        stage[w][lane +  32] = v1;
        stage[w][lane +  64] = v2;
        stage[w][lane +  96] = v3;
        stage[w][lane + 128] = v4;
        __syncwarp();
        float4 q0 = stage[w][lane * 5    ];
        float4 q1 = stage[w][lane * 5 + 1];
        float4 q2 = stage[w][lane * 5 + 2];
        float4 q3 = stage[w][lane * 5 + 3];
        float4 q4 = stage[w][lane * 5 + 4];

        float r[2][CC] = {
            { q0.x, q0.y, q0.z, q0.w, q1.x, q1.y, q1.z, q1.w, q2.x, q2.y },
            { q2.z, q2.w, q3.x, q3.y, q3.z, q3.w, q4.x, q4.y, q4.z, q4.w }
        };
#pragma unroll
        for (int rr = 0; rr < 2; rr++) {
            float e[CC], s = 0.f;
#pragma unroll
            for (int i = 0; i < CC; i++) { e[i] = __expf(r[rr][i]); s += e[i]; }
            float inv = __fdividef(1.f, s);
            sM += __logf(s);
#pragma unroll
            for (int i = 0; i < CC; i++) {
                float p  = e[i] * inv;
                ap [i] += p;
                ap2[i]  = fmaf(p, p, ap2[i]);
                sv [i] += r[rr][i];
            }
        }
    }

    // tail rows (none for n % 64 == 0, kept for generality)
    for (int r0 = (nTiles << 6) + blockIdx.x * blockDim.x + threadIdx.x; r0 < n;
         r0 += gridDim.x * blockDim.x) {
        const float2* row = reinterpret_cast<const float2*>(x) + r0 * 5;
        float v[CC];
#pragma unroll
        for (int j = 0; j < 5; j++) { float2 t2 = row[j]; v[2*j] = t2.x; v[2*j+1] = t2.y; }
        float e[CC], s = 0.f;
#pragma unroll
        for (int i = 0; i < CC; i++) { e[i] = __expf(v[i]); s += e[i]; }
        float inv = __fdividef(1.f, s);
        sM += __logf(s);
#pragma unroll
        for (int i = 0; i < CC; i++) {
            float p = e[i] * inv;
            ap[i] += p; ap2[i] = fmaf(p, p, ap2[i]); sv[i] += v[i];
        }
    }

    // ---- block reduction: 31 stats -> double partials ----
#pragma unroll
    for (int i = 0; i < CC; i++) {
#pragma unroll
        for (int o = 16; o > 0; o >>= 1) {
            ap [i] += __shfl_down_sync(0xffffffffu, ap [i], o);
            ap2[i] += __shfl_down_sync(0xffffffffu, ap2[i], o);
            sv [i] += __shfl_down_sync(0xffffffffu, sv [i], o);
        }
    }
#pragma unroll
    for (int o = 16; o > 0; o >>= 1) sM += __shfl_down_sync(0xffffffffu, sM, o);

    __shared__ float sh[31][WARPS_PER_BLOCK];
    if (lane == 0) {
#pragma unroll
        for (int i = 0; i < CC; i++) {
            sh[i     ][w] = ap [i];
            sh[10 + i][w] = ap2[i];
            sh[20 + i][w] = sv [i];
        }
        sh[30][w] = sM;
    }
    __syncthreads();
    if (threadIdx.x < 31) {
        double s2 = 0.0;
#pragma unroll
        for (int w2 = 0; w2 < WARPS_PER_BLOCK; w2++) s2 += (double)sh[threadIdx.x][w2];
        g_partials[blockIdx.x][threadIdx.x] = s2;
    }
}

// ---------------------------------------------------------------------------
// Fused branchless digamma + trigamma (shift to x+6 + asymptotic series).
// ---------------------------------------------------------------------------
__device__ __forceinline__ void psi01(float x, float& dg, float& tg) {
    float s0 = 0.f, s1 = 0.f;
#pragma unroll
    for (int k = 0; k < 6; k++) {
        float r = __fdividef(1.f, x + (float)k);
        s0 += r;
        s1  = fmaf(r, r, s1);
    }
    float y  = x + 6.f;
    float r  = __fdividef(1.f, y);
    float r2 = r * r;
    dg = __logf(y) - 0.5f * r
       - r2 * (0.0833333333f - r2 * (0.0083333333f - r2 * 0.0039682540f))
       - s0;
    tg = r + 0.5f * r2
       + r * r2 * (0.1666666667f - r2 * (0.0333333333f - r2 * 0.0238095238f))
       + s1;
}

__device__ __forceinline__ void allred2_16(float& v1, float& v2) {
#pragma unroll
    for (int o = 8; o > 0; o >>= 1) {
        v1 += __shfl_xor_sync(0xffffffffu, v1, o);
        v2 += __shfl_xor_sync(0xffffffffu, v2, o);
    }
}
__device__ __forceinline__ float allred1_16(float v) {
#pragma unroll
    for (int o = 8; o > 0; o >>= 1) v += __shfl_xor_sync(0xffffffffu, v, o);
    return v;
}

// ---------------------------------------------------------------------------
// Kernel 2: reduce partials (warp per stat) + Newton (fixed 20 iterations,
// single allreduce per iteration).
// ---------------------------------------------------------------------------
__global__ __launch_bounds__(1024) void ed_solve(float* __restrict__ out, int n) {
    __shared__ double st[32];
    const int tid  = threadIdx.x;
    const int w    = tid >> 5;
    const int lane = tid & 31;

    if (w < 31) {
        double s = 0.0;
        for (int b = lane; b < GRID; b += 32) s += g_partials[b][w];
#pragma unroll
        for (int o = 16; o > 0; o >>= 1) s += __shfl_down_sync(0xffffffffu, s, o);
        if (lane == 0) st[w] = s;
    }
    __syncthreads();

    if (w == 0) {
        const bool  act = (lane < CC);
        const double dn = (double)n;

        float m1  = act ? (float)(st[lane]      / dn) : 0.f;
        float m2  = act ? (float)(st[10 + lane] / dn) : 0.f;
        // sum log p[i] = sum_v[i] - sum_M
        float lpa = act ? (float)((st[20 + lane] - st[30]) / dn) : 0.f;

        float ratio = act ? (m1 - m2) / (m2 - m1 * m1) : 0.f;
        float rmean = allred1_16(ratio) * 0.1f;
        float a     = act ? m1 * rmean : 0.f;
        float asum  = allred1_16(a);
        if (!act) { a = 1.0f; asum = 20.0f; }

        // Newton, rank-1 Hessian inverse; n cancels.
        // sum(delta) = num - b*qs -> next asum needs no extra reduce.
#pragma unroll 1
        for (int k = 0; k < 20; k++) {
            float dga, tga, dgs, tgs;
            psi01(a,    dga, tga);
            psi01(asum, dgs, tgs);
            float g    = dgs - dga + lpa;
            float qinv = __fdividef(-1.f, tga);
            float num  = act ? g * qinv : 0.f;
            float qs   = act ? qinv     : 0.f;
            allred2_16(num, qs);
            float zinv = __fdividef(1.f, tgs);
            float b    = num / (zinv + qs);
            a    = act ? a - (g - b) * qinv : 1.0f;
            asum = act ? asum - (num - b * qs) : 20.0f;
        }
        if (act) out[lane] = a;
    }
}

// ---------------------------------------------------------------------------
extern "C" void kernel_launch(void* const* d_in, const int* in_sizes, int n_in,
                              void* d_out, int out_size) {
    const float* x = (const float*)d_in[0];
    const int n = in_sizes[0] / CC;   // 2,000,000 rows
    ed_stats<<<GRID, BLOCK>>>(x, n);
    ed_solve<<<1, 1024>>>((float*)d_out, n);
}

// round 7
// speedup vs baseline: 1.0052x; 1.0052x over previous
#include <cuda_runtime.h>
#include <math.h>

#define CC 10

static const int BLOCK = 256;
static const int GRID  = 1184;
static const int WARPS_PER_BLOCK = 8;
static const int NWARPS = GRID * WARPS_PER_BLOCK;

// Per-block partials: [block][stat], 0..9 = sum p, 10..19 = sum p^2,
// 20..29 = sum logits v, 30 = sum of per-row log-sum-exp M.
// (sum log p[i] = sum_v[i] - sum_M)
__device__ double g_partials[GRID][32];

// ---------------------------------------------------------------------------
// Kernel 1: stats with warp-level shared staging.
// Each warp-tile = 64 rows = 160 float4 = 2560B: coalesced LDG.128 -> STS.128
// linear -> each lane LDS.128 x5 for its 2 contiguous rows (80B aligned).
// ---------------------------------------------------------------------------
__global__ __launch_bounds__(256, 3) void ed_stats(const float* __restrict__ x, int n) {
    __shared__ float4 stage[WARPS_PER_BLOCK][160];

    const int lane = threadIdx.x & 31;
    const int w    = threadIdx.x >> 5;
    const int gw   = blockIdx.x * WARPS_PER_BLOCK + w;

    float ap [CC];   // sum p
    float ap2[CC];   // sum p^2
    float sv [CC];   // sum v (logits)
    float sM = 0.f;  // sum log-sum-exp
#pragma unroll
    for (int i = 0; i < CC; i++) { ap[i] = 0.f; ap2[i] = 0.f; sv[i] = 0.f; }

    const float4* __restrict__ x4 = reinterpret_cast<const float4*>(x);
    const int nTiles = n >> 6;   // 64 rows per tile

    for (int t = gw; t < nTiles; t += NWARPS) {
        const float4* src = x4 + (size_t)t * 160;
        float4 v0 = src[lane      ];
        float4 v1 = src[lane +  32];
        float4 v2 = src[lane +  64];
        float4 v3 = src[lane +  96];
        float4 v4 = src[lane + 128];
        __syncwarp();                    // prior tile fully consumed
        stage[w][lane      ] = v0;
        stage[w][lane +  32] = v1;
        stage[w][lane +  64] = v2;
        stage[w][lane +  96] = v3;
        stage[w][lane + 128] = v4;
        __syncwarp();
        float4 q0 = stage[w][lane * 5    ];
        float4 q1 = stage[w][lane * 5 + 1];
        float4 q2 = stage[w][lane * 5 + 2];
        float4 q3 = stage[w][lane * 5 + 3];
        float4 q4 = stage[w][lane * 5 + 4];

        float r[2][CC] = {
            { q0.x, q0.y, q0.z, q0.w, q1.x, q1.y, q1.z, q1.w, q2.x, q2.y },
            { q2.z, q2.w, q3.x, q3.y, q3.z, q3.w, q4.x, q4.y, q4.z, q4.w }
        };
#pragma unroll
        for (int rr = 0; rr < 2; rr++) {
            float e[CC], s = 0.f;
#pragma unroll
            for (int i = 0; i < CC; i++) { e[i] = __expf(r[rr][i]); s += e[i]; }
            float inv = __fdividef(1.f, s);
            sM += __logf(s);
#pragma unroll
            for (int i = 0; i < CC; i++) {
                float p  = e[i] * inv;
                ap [i] += p;
                ap2[i]  = fmaf(p, p, ap2[i]);
                sv [i] += r[rr][i];
            }
        }
    }

    // tail rows (none for n % 64 == 0, kept for generality)
    for (int r0 = (nTiles << 6) + blockIdx.x * blockDim.x + threadIdx.x; r0 < n;
         r0 += gridDim.x * blockDim.x) {
        const float2* row = reinterpret_cast<const float2*>(x) + r0 * 5;
        float v[CC];
#pragma unroll
        for (int j = 0; j < 5; j++) { float2 t2 = row[j]; v[2*j] = t2.x; v[2*j+1] = t2.y; }
        float e[CC], s = 0.f;
#pragma unroll
        for (int i = 0; i < CC; i++) { e[i] = __expf(v[i]); s += e[i]; }
        float inv = __fdividef(1.f, s);
        sM += __logf(s);
#pragma unroll
        for (int i = 0; i < CC; i++) {
            float p = e[i] * inv;
            ap[i] += p; ap2[i] = fmaf(p, p, ap2[i]); sv[i] += v[i];
        }
    }

    // ---- block reduction: 31 stats -> double partials ----
#pragma unroll
    for (int i = 0; i < CC; i++) {
#pragma unroll
        for (int o = 16; o > 0; o >>= 1) {
            ap [i] += __shfl_down_sync(0xffffffffu, ap [i], o);
            ap2[i] += __shfl_down_sync(0xffffffffu, ap2[i], o);
            sv [i] += __shfl_down_sync(0xffffffffu, sv [i], o);
        }
    }
#pragma unroll
    for (int o = 16; o > 0; o >>= 1) sM += __shfl_down_sync(0xffffffffu, sM, o);

    __shared__ float sh[31][WARPS_PER_BLOCK];
    if (lane == 0) {
#pragma unroll
        for (int i = 0; i < CC; i++) {
            sh[i     ][w] = ap [i];
            sh[10 + i][w] = ap2[i];
            sh[20 + i][w] = sv [i];
        }
        sh[30][w] = sM;
    }
    __syncthreads();
    if (threadIdx.x < 31) {
        double s2 = 0.0;
#pragma unroll
        for (int w2 = 0; w2 < WARPS_PER_BLOCK; w2++) s2 += (double)sh[threadIdx.x][w2];
        g_partials[blockIdx.x][threadIdx.x] = s2;
    }
}

// ---------------------------------------------------------------------------
// Fused branchless digamma + trigamma (shift to x+6 + asymptotic series).
// ---------------------------------------------------------------------------
__device__ __forceinline__ void psi01(float x, float& dg, float& tg) {
    float s0 = 0.f, s1 = 0.f;
#pragma unroll
    for (int k = 0; k < 6; k++) {
        float r = __fdividef(1.f, x + (float)k);
        s0 += r;
        s1  = fmaf(r, r, s1);
    }
    float y  = x + 6.f;
    float r  = __fdividef(1.f, y);
    float r2 = r * r;
    dg = __logf(y) - 0.5f * r
       - r2 * (0.0833333333f - r2 * (0.0083333333f - r2 * 0.0039682540f))
       - s0;
    tg = r + 0.5f * r2
       + r * r2 * (0.1666666667f - r2 * (0.0333333333f - r2 * 0.0238095238f))
       + s1;
}

__device__ __forceinline__ void allred2_16(float& v1, float& v2) {
#pragma unroll
    for (int o = 8; o > 0; o >>= 1) {
        v1 += __shfl_xor_sync(0xffffffffu, v1, o);
        v2 += __shfl_xor_sync(0xffffffffu, v2, o);
    }
}
__device__ __forceinline__ float allred1_16(float v) {
#pragma unroll
    for (int o = 8; o > 0; o >>= 1) v += __shfl_xor_sync(0xffffffffu, v, o);
    return v;
}

// ---------------------------------------------------------------------------
// Kernel 2: reduce partials (warp per stat) + Newton (fixed 20 iterations,
// single allreduce per iteration).
// ---------------------------------------------------------------------------
__global__ __launch_bounds__(1024) void ed_solve(float* __restrict__ out, int n) {
    __shared__ double st[32];
    const int tid  = threadIdx.x;
    const int w    = tid >> 5;
    const int lane = tid & 31;

    if (w < 31) {
        double s = 0.0;
        for (int b = lane; b < GRID; b += 32) s += g_partials[b][w];
#pragma unroll
        for (int o = 16; o > 0; o >>= 1) s += __shfl_down_sync(0xffffffffu, s, o);
        if (lane == 0) st[w] = s;
    }
    __syncthreads();

    if (w == 0) {
        const bool  act = (lane < CC);
        const double dn = (double)n;

        float m1  = act ? (float)(st[lane]      / dn) : 0.f;
        float m2  = act ? (float)(st[10 + lane] / dn) : 0.f;
        // sum log p[i] = sum_v[i] - sum_M
        float lpa = act ? (float)((st[20 + lane] - st[30]) / dn) : 0.f;

        float ratio = act ? (m1 - m2) / (m2 - m1 * m1) : 0.f;
        float rmean = allred1_16(ratio) * 0.1f;
        float a     = act ? m1 * rmean : 0.f;
        float asum  = allred1_16(a);
        if (!act) { a = 1.0f; asum = 20.0f; }

        // Newton, rank-1 Hessian inverse; n cancels.
        // sum(delta) = num - b*qs -> next asum needs no extra reduce.
#pragma unroll 1
        for (int k = 0; k < 20; k++) {
            float dga, tga, dgs, tgs;
            psi01(a,    dga, tga);
            psi01(asum, dgs, tgs);
            float g    = dgs - dga + lpa;
            float qinv = __fdividef(-1.f, tga);
            float num  = act ? g * qinv : 0.f;
            float qs   = act ? qinv     : 0.f;
            allred2_16(num, qs);
            float zinv = __fdividef(1.f, tgs);
            float b    = num / (zinv + qs);
            a    = act ? a - (g - b) * qinv : 1.0f;
            asum = act ? asum - (num - b * qs) : 20.0f;
        }
        if (act) out[lane] = a;
    }
}

// ---------------------------------------------------------------------------
extern "C" void kernel_launch(void* const* d_in, const int* in_sizes, int n_in,
                              void* d_out, int out_size) {
    const float* x = (const float*)d_in[0];
    const int n = in_sizes[0] / CC;   // 2,000,000 rows
    ed_stats<<<GRID, BLOCK>>>(x, n);
    ed_solve<<<1, 1024>>>((float*)d_out, n);
}

// round 8
// speedup vs baseline: 1.1420x; 1.1362x over previous
#include <cuda_runtime.h>
#include <math.h>
#include <stdint.h>

#define CC 10

static const int BLOCK = 256;
static const int GRID  = 1184;
static const int WPB   = 8;                 // warps per block
static const int NWARPS = GRID * WPB;

// Per-block partials: 0..9 sum p, 10..19 sum p^2, 20..29 sum v, 30 sum logsumexp
__device__ double g_partials[GRID][32];

// ---------------------------------------------------------------------------
__device__ __forceinline__ uint32_t smem_u32(const void* p) {
    uint32_t a;
    asm("{ .reg .u64 t; cvta.to.shared.u64 t, %1; cvt.u32.u64 %0, t; }"
        : "=r"(a) : "l"(p));
    return a;
}
__device__ __forceinline__ void cp16(uint32_t s, const void* g) {
    asm volatile("cp.async.cg.shared.global [%0], [%1], 16;" :: "r"(s), "l"(g));
}
#define CP_COMMIT() asm volatile("cp.async.commit_group;")
#define CP_WAIT1()  asm volatile("cp.async.wait_group 1;")

// ---------------------------------------------------------------------------
// Kernel 1: stats with cp.async double-buffered warp staging.
// Tile = 64 rows = 160 float4 per warp. Each lane copies 5 float4 (coalesced),
// then reads back its own 2 rows (5x LDS.128 at lane*80B, conflict-free).
// ---------------------------------------------------------------------------
__global__ __launch_bounds__(256) void ed_stats(const float* __restrict__ x, int n) {
    __shared__ float4 stage[WPB][2][160];   // 40KB static

    const int lane = threadIdx.x & 31;
    const int w    = threadIdx.x >> 5;
    const int gw   = blockIdx.x * WPB + w;

    float ap [CC], ap2[CC], sv[CC];
    float sM = 0.f;
#pragma unroll
    for (int i = 0; i < CC; i++) { ap[i] = 0.f; ap2[i] = 0.f; sv[i] = 0.f; }

    const float4* __restrict__ x4 = reinterpret_cast<const float4*>(x);
    const int nT = n >> 6;

    const uint32_t sb0 = smem_u32(&stage[w][0][0]);
    const uint32_t sb1 = smem_u32(&stage[w][1][0]);

    // prologue: stage first tile into buffer 0
    int t = gw;
    if (t < nT) {
        const float4* src = x4 + (size_t)t * 160;
#pragma unroll
        for (int j = 0; j < 5; j++)
            cp16(sb0 + (uint32_t)(lane + j * 32) * 16u, src + lane + j * 32);
    }
    CP_COMMIT();

    int cur = 0;
    for (; t < nT; t += NWARPS) {
        // issue next tile into the other buffer before consuming this one
        const int t2 = t + NWARPS;
        const uint32_t sbn = cur ? sb0 : sb1;
        if (t2 < nT) {
            const float4* src = x4 + (size_t)t2 * 160;
#pragma unroll
            for (int j = 0; j < 5; j++)
                cp16(sbn + (uint32_t)(lane + j * 32) * 16u, src + lane + j * 32);
        }
        CP_COMMIT();
        CP_WAIT1();        // current tile's group complete (this thread)
        __syncwarp();      // ... and every lane's

        const float4* b = &stage[w][cur][0];
        float4 q0 = b[lane * 5    ];
        float4 q1 = b[lane * 5 + 1];
        float4 q2 = b[lane * 5 + 2];
        float4 q3 = b[lane * 5 + 3];
        float4 q4 = b[lane * 5 + 4];

        float v0[CC] = { q0.x, q0.y, q0.z, q0.w, q1.x, q1.y, q1.z, q1.w, q2.x, q2.y };
        float v1[CC] = { q2.z, q2.w, q3.x, q3.y, q3.z, q3.w, q4.x, q4.y, q4.z, q4.w };

        {
            float e[CC], s = 0.f;
#pragma unroll
            for (int i = 0; i < CC; i++) { e[i] = __expf(v0[i]); s += e[i]; }
            float inv = __fdividef(1.f, s);
            sM += __logf(s);
#pragma unroll
            for (int i = 0; i < CC; i++) {
                float p = e[i] * inv;
                ap[i] += p; ap2[i] = fmaf(p, p, ap2[i]); sv[i] += v0[i];
            }
        }
        {
            float e[CC], s = 0.f;
#pragma unroll
            for (int i = 0; i < CC; i++) { e[i] = __expf(v1[i]); s += e[i]; }
            float inv = __fdividef(1.f, s);
            sM += __logf(s);
#pragma unroll
            for (int i = 0; i < CC; i++) {
                float p = e[i] * inv;
                ap[i] += p; ap2[i] = fmaf(p, p, ap2[i]); sv[i] += v1[i];
            }
        }

        __syncwarp();      // everyone done reading buf[cur] before it is refilled
        cur ^= 1;
    }

    // tail rows (n % 64 != 0 — none for n = 2M, kept for generality)
    for (int r0 = (nT << 6) + blockIdx.x * blockDim.x + threadIdx.x; r0 < n;
         r0 += gridDim.x * blockDim.x) {
        const float2* row = reinterpret_cast<const float2*>(x) + r0 * 5;
        float v[CC];
#pragma unroll
        for (int j = 0; j < 5; j++) { float2 t2 = row[j]; v[2*j] = t2.x; v[2*j+1] = t2.y; }
        float e[CC], s = 0.f;
#pragma unroll
        for (int i = 0; i < CC; i++) { e[i] = __expf(v[i]); s += e[i]; }
        float inv = __fdividef(1.f, s);
        sM += __logf(s);
#pragma unroll
        for (int i = 0; i < CC; i++) {
            float p = e[i] * inv;
            ap[i] += p; ap2[i] = fmaf(p, p, ap2[i]); sv[i] += v[i];
        }
    }

    // ---- block reduction: 31 stats -> double partials ----
#pragma unroll
    for (int i = 0; i < CC; i++) {
#pragma unroll
        for (int o = 16; o > 0; o >>= 1) {
            ap [i] += __shfl_down_sync(0xffffffffu, ap [i], o);
            ap2[i] += __shfl_down_sync(0xffffffffu, ap2[i], o);
            sv [i] += __shfl_down_sync(0xffffffffu, sv [i], o);
        }
    }
#pragma unroll
    for (int o = 16; o > 0; o >>= 1) sM += __shfl_down_sync(0xffffffffu, sM, o);

    __shared__ float sh[31][WPB];
    if (lane == 0) {
#pragma unroll
        for (int i = 0; i < CC; i++) {
            sh[i     ][w] = ap [i];
            sh[10 + i][w] = ap2[i];
            sh[20 + i][w] = sv [i];
        }
        sh[30][w] = sM;
    }
    __syncthreads();
    if (threadIdx.x < 31) {
        double s2 = 0.0;
#pragma unroll
        for (int w2 = 0; w2 < WPB; w2++) s2 += (double)sh[threadIdx.x][w2];
        g_partials[blockIdx.x][threadIdx.x] = s2;
    }
}

// ---------------------------------------------------------------------------
// Fused branchless digamma + trigamma (shift to x+6 + asymptotic series).
// ---------------------------------------------------------------------------
__device__ __forceinline__ void psi01(float x, float& dg, float& tg) {
    float s0 = 0.f, s1 = 0.f;
#pragma unroll
    for (int k = 0; k < 6; k++) {
        float r = __fdividef(1.f, x + (float)k);
        s0 += r;
        s1  = fmaf(r, r, s1);
    }
    float y  = x + 6.f;
    float r  = __fdividef(1.f, y);
    float r2 = r * r;
    dg = __logf(y) - 0.5f * r
       - r2 * (0.0833333333f - r2 * (0.0083333333f - r2 * 0.0039682540f))
       - s0;
    tg = r + 0.5f * r2
       + r * r2 * (0.1666666667f - r2 * (0.0333333333f - r2 * 0.0238095238f))
       + s1;
}

__device__ __forceinline__ void allred2_16(float& v1, float& v2) {
#pragma unroll
    for (int o = 8; o > 0; o >>= 1) {
        v1 += __shfl_xor_sync(0xffffffffu, v1, o);
        v2 += __shfl_xor_sync(0xffffffffu, v2, o);
    }
}
__device__ __forceinline__ float allred1_16(float v) {
#pragma unroll
    for (int o = 8; o > 0; o >>= 1) v += __shfl_xor_sync(0xffffffffu, v, o);
    return v;
}

// ---------------------------------------------------------------------------
// Kernel 2: reduce partials (warp per stat) + Newton, fixed 10 iterations.
// ---------------------------------------------------------------------------
__global__ __launch_bounds__(1024) void ed_solve(float* __restrict__ out, int n) {
    __shared__ double st[32];
    const int tid  = threadIdx.x;
    const int w    = tid >> 5;
    const int lane = tid & 31;

    if (w < 31) {
        double s = 0.0;
        for (int b = lane; b < GRID; b += 32) s += g_partials[b][w];
#pragma unroll
        for (int o = 16; o > 0; o >>= 1) s += __shfl_down_sync(0xffffffffu, s, o);
        if (lane == 0) st[w] = s;
    }
    __syncthreads();

    if (w == 0) {
        const bool  act = (lane < CC);
        const double dn = (double)n;

        float m1  = act ? (float)(st[lane]      / dn) : 0.f;
        float m2  = act ? (float)(st[10 + lane] / dn) : 0.f;
        float lpa = act ? (float)((st[20 + lane] - st[30]) / dn) : 0.f;

        float ratio = act ? (m1 - m2) / (m2 - m1 * m1) : 0.f;
        float rmean = allred1_16(ratio) * 0.1f;
        float a     = act ? m1 * rmean : 0.f;
        float asum  = allred1_16(a);
        if (!act) { a = 1.0f; asum = 20.0f; }

        // Newton, rank-1 Hessian inverse; n cancels.
        // sum(delta) = num - b*qs -> next asum needs no extra reduce.
#pragma unroll 1
        for (int k = 0; k < 10; k++) {
            float dga, tga, dgs, tgs;
            psi01(a,    dga, tga);
            psi01(asum, dgs, tgs);
            float g    = dgs - dga + lpa;
            float qinv = __fdividef(-1.f, tga);
            float num  = act ? g * qinv : 0.f;
            float qs   = act ? qinv     : 0.f;
            allred2_16(num, qs);
            float zinv = __fdividef(1.f, tgs);
            float b    = num / (zinv + qs);
            a    = act ? a - (g - b) * qinv : 1.0f;
            asum = act ? asum - (num - b * qs) : 20.0f;
        }
        if (act) out[lane] = a;
    }
}

// ---------------------------------------------------------------------------
extern "C" void kernel_launch(void* const* d_in, const int* in_sizes, int n_in,
                              void* d_out, int out_size) {
    const float* x = (const float*)d_in[0];
    const int n = in_sizes[0] / CC;   // 2,000,000 rows
    ed_stats<<<GRID, BLOCK>>>(x, n);
    ed_solve<<<1, 1024>>>((float*)d_out, n);
}